// round 14
// baseline (speedup 1.0000x reference)
#include <cuda_runtime.h>
#include <cuda_bf16.h>
#include <math.h>
#include <stdint.h>

// Problem dims (fixed by the dataset)
#define BATCH   32
#define STEPS   1024      // T
#define HD      1024      // D == H
#define BT      32768     // BATCH*STEPS rows
#define NCTA    128       // scan grid: 4 groups x 32 CTAs
#define GRP_CTAS 32

// ---------------- scratch (no allocations allowed) ----------------
__device__ float         g_xproj[(size_t)BT * HD];     // 128 MB input-proj result
__device__ unsigned int  g_bar2[4][STEPS];             // per-group per-step barrier counters
__device__ __nv_bfloat16 g_Ahi[(size_t)BT * HD];       // 64 MB (seq split)
__device__ __nv_bfloat16 g_Alo[(size_t)BT * HD];       // 64 MB
__device__ __nv_bfloat16 g_Bhi[HD * HD];               // 2 MB
__device__ __nv_bfloat16 g_Blo[HD * HD];               // 2 MB
// fragment-order h exchange: [parity][grp] -> 64 k-groups x 8 b x 64 B
__device__ uint8_t       g_ex[2][4][64 * 8 * 64];      // 256 KB total

// =================================================================
// helpers (plain sm_80-era PTX only)
// =================================================================
__device__ __forceinline__ uint32_t smem_u32(const void* p) {
    uint32_t a;
    asm("{ .reg .u64 t; cvta.to.shared.u64 t, %1; cvt.u32.u64 %0, t; }" : "=r"(a) : "l"(p));
    return a;
}
__device__ __forceinline__ void cp_async16(uint32_t dst, const void* src) {
    asm volatile("cp.async.cg.shared.global [%0], [%1], 16;" :: "r"(dst), "l"(src));
}
__device__ __forceinline__ void cp_commit() {
    asm volatile("cp.async.commit_group;");
}
__device__ __forceinline__ void cp_wait1() {
    asm volatile("cp.async.wait_group 1;");
}
__device__ __forceinline__ void ldsm_x4(uint32_t* r, uint32_t addr) {
    asm volatile("ldmatrix.sync.aligned.m8n8.x4.shared.b16 {%0,%1,%2,%3}, [%4];"
                 : "=r"(r[0]), "=r"(r[1]), "=r"(r[2]), "=r"(r[3]) : "r"(addr));
}
__device__ __forceinline__ void mma_bf16(float* c, const uint32_t* a, const uint32_t* b) {
    asm volatile(
        "mma.sync.aligned.m16n8k16.row.col.f32.bf16.bf16.f32 "
        "{%0,%1,%2,%3}, {%4,%5,%6,%7}, {%8,%9}, {%0,%1,%2,%3};"
        : "+f"(c[0]), "+f"(c[1]), "+f"(c[2]), "+f"(c[3])
        : "r"(a[0]), "r"(a[1]), "r"(a[2]), "r"(a[3]), "r"(b[0]), "r"(b[1]));
}
__device__ __forceinline__ void mma_bf16_2(float* c, const uint32_t* a,
                                           uint32_t b0, uint32_t b1) {
    asm volatile(
        "mma.sync.aligned.m16n8k16.row.col.f32.bf16.bf16.f32 "
        "{%0,%1,%2,%3}, {%4,%5,%6,%7}, {%8,%9}, {%0,%1,%2,%3};"
        : "+f"(c[0]), "+f"(c[1]), "+f"(c[2]), "+f"(c[3])
        : "r"(a[0]), "r"(a[1]), "r"(a[2]), "r"(a[3]), "r"(b0), "r"(b1));
}

// =================================================================
// split fp32 -> bf16 hi + bf16 lo
// =================================================================
__global__ void split_bf16(const float* __restrict__ in,
                           __nv_bfloat16* __restrict__ hi,
                           __nv_bfloat16* __restrict__ lo, int n4) {
    int i = blockIdx.x * blockDim.x + threadIdx.x;
    if (i >= n4) return;
    float4 v = ((const float4*)in)[i];
    __nv_bfloat16 h0 = __float2bfloat16(v.x);
    __nv_bfloat16 h1 = __float2bfloat16(v.y);
    __nv_bfloat16 h2 = __float2bfloat16(v.z);
    __nv_bfloat16 h3 = __float2bfloat16(v.w);
    __nv_bfloat16 l0 = __float2bfloat16(v.x - __bfloat162float(h0));
    __nv_bfloat16 l1 = __float2bfloat16(v.y - __bfloat162float(h1));
    __nv_bfloat16 l2 = __float2bfloat16(v.z - __bfloat162float(h2));
    __nv_bfloat16 l3 = __float2bfloat16(v.w - __bfloat162float(h3));
    ((__nv_bfloat162*)hi)[2 * i + 0] = __halves2bfloat162(h0, h1);
    ((__nv_bfloat162*)hi)[2 * i + 1] = __halves2bfloat162(h2, h3);
    ((__nv_bfloat162*)lo)[2 * i + 0] = __halves2bfloat162(l0, l1);
    ((__nv_bfloat162*)lo)[2 * i + 1] = __halves2bfloat162(l2, l3);
}

// =================================================================
// HMMA split-bf16 GEMM (NT)  -- unchanged (passing since R4)
// =================================================================
#define GSTAGES 3
#define TILE_B   10240
#define STAGE_B  (4 * TILE_B)
#define ROWB     80

__global__ __launch_bounds__(256)
void mma_gemm(const __nv_bfloat16* __restrict__ Ahi, const __nv_bfloat16* __restrict__ Alo,
              const __nv_bfloat16* __restrict__ Bhi, const __nv_bfloat16* __restrict__ Blo,
              const float* __restrict__ bias, float* __restrict__ C) {
    extern __shared__ char dsm[];
    const uint32_t sb = smem_u32(dsm);

    const int tid = threadIdx.x;
    const int wid = tid >> 5;
    const int lane = tid & 31;
    const int bm = blockIdx.y * 128;
    const int bn = blockIdx.x * 128;
    const int wm = (wid >> 2) * 64;
    const int wn = (wid & 3) * 32;

    const int lt  = tid >> 6;
    const int lid = tid & 63;
    const __nv_bfloat16* lsrc = (lt == 0) ? Ahi : (lt == 1) ? Alo : (lt == 2) ? Bhi : Blo;
    const int lrowb = (lt < 2) ? bm : bn;

    float acc[4][4][4];
#pragma unroll
    for (int i = 0; i < 4; i++)
#pragma unroll
        for (int j = 0; j < 4; j++)
#pragma unroll
            for (int e = 0; e < 4; e++) acc[i][j][e] = 0.f;

#pragma unroll
    for (int ps = 0; ps < GSTAGES - 1; ps++) {
        uint32_t dstb = sb + ps * STAGE_B + lt * TILE_B;
#pragma unroll
        for (int i = 0; i < 8; i++) {
            int idx = i * 64 + lid;
            int r = idx >> 2, c = idx & 3;
            cp_async16(dstb + r * ROWB + c * 16,
                       lsrc + (size_t)(lrowb + r) * HD + ps * 32 + c * 8);
        }
        cp_commit();
    }

    for (int kt = 0; kt < HD / 32; kt++) {
        cp_wait1();
        __syncthreads();

        if (kt + GSTAGES - 1 < HD / 32) {
            uint32_t dstb = sb + ((kt + GSTAGES - 1) % GSTAGES) * STAGE_B + lt * TILE_B;
#pragma unroll
            for (int i = 0; i < 8; i++) {
                int idx = i * 64 + lid;
                int r = idx >> 2, c = idx & 3;
                cp_async16(dstb + r * ROWB + c * 16,
                           lsrc + (size_t)(lrowb + r) * HD + (kt + GSTAGES - 1) * 32 + c * 8);
            }
        }
        cp_commit();

        uint32_t stg = sb + (kt % GSTAGES) * STAGE_B;
        uint32_t aBaseH = stg + 0 * TILE_B;
        uint32_t aBaseL = stg + 1 * TILE_B;
        uint32_t bBaseH = stg + 2 * TILE_B;
        uint32_t bBaseL = stg + 3 * TILE_B;

#pragma unroll
        for (int ks = 0; ks < 2; ks++) {
            uint32_t ah[4][4], al[4][4], bh[4][2], bl[4][2];
            int arow = (lane & 15);
            int acol = (lane >> 4) * 16 + ks * 32;
#pragma unroll
            for (int mt = 0; mt < 4; mt++) {
                ldsm_x4(ah[mt], aBaseH + (wm + mt * 16 + arow) * ROWB + acol);
                ldsm_x4(al[mt], aBaseL + (wm + mt * 16 + arow) * ROWB + acol);
            }
            int brow = ((lane >> 4) << 3) + (lane & 7);
            int bcol = ((lane >> 3) & 1) * 16 + ks * 32;
#pragma unroll
            for (int p = 0; p < 2; p++) {
                uint32_t t[4];
                ldsm_x4(t, bBaseH + (wn + p * 16 + brow) * ROWB + bcol);
                bh[2 * p][0] = t[0]; bh[2 * p][1] = t[1];
                bh[2 * p + 1][0] = t[2]; bh[2 * p + 1][1] = t[3];
                ldsm_x4(t, bBaseL + (wn + p * 16 + brow) * ROWB + bcol);
                bl[2 * p][0] = t[0]; bl[2 * p][1] = t[1];
                bl[2 * p + 1][0] = t[2]; bl[2 * p + 1][1] = t[3];
            }
#pragma unroll
            for (int mt = 0; mt < 4; mt++)
#pragma unroll
                for (int nt = 0; nt < 4; nt++) {
                    mma_bf16(acc[mt][nt], ah[mt], bh[nt]);
                    mma_bf16(acc[mt][nt], ah[mt], bl[nt]);
                    mma_bf16(acc[mt][nt], al[mt], bh[nt]);
                }
        }
    }

#pragma unroll
    for (int mt = 0; mt < 4; mt++) {
#pragma unroll
        for (int nt = 0; nt < 4; nt++) {
            int m0 = bm + wm + mt * 16 + (lane >> 2);
            int n0 = bn + wn + nt * 8 + (lane & 3) * 2;
            float b0 = bias[n0], b1 = bias[n0 + 1];
            float2 v0 = make_float2(acc[mt][nt][0] + b0, acc[mt][nt][1] + b1);
            float2 v1 = make_float2(acc[mt][nt][2] + b0, acc[mt][nt][3] + b1);
            *(float2*)&C[(size_t)m0 * HD + n0] = v0;
            *(float2*)&C[(size_t)(m0 + 8) * HD + n0] = v1;
        }
    }
}

// =================================================================
// Persistent recurrent scan v8: merged Wh+Wo MMA block, one spill round,
//  early publish/release, frag prefetch overlapped with epilogue work.
// =================================================================
__device__ __forceinline__ float gelu_exact(float x) {
    return 0.5f * x * (1.0f + erff(x * 0.70710678118654752f));
}

#define SROW       2064      // padded weight smem row (1032 bf16)
#define OFF_WHI    0
#define OFF_WLO    66048     // 32*2064
#define OFF_PART   132096
#define SPW        264       // floats per warp partial row
#define SCAN_SMEM  (OFF_PART + 32 * SPW * 4)   // 165888 B (2 planes)

__global__ __launch_bounds__(512)
void scan_kernel(const float* __restrict__ xproj,
                 const float* __restrict__ Wh,
                 const float* __restrict__ Wo,
                 const float* __restrict__ bo,
                 float* __restrict__ hidden,
                 float* __restrict__ outproj) {
    extern __shared__ char smem[];
    const uint32_t sb = smem_u32(smem);
    float* sPart1 = (float*)(smem + OFF_PART);
    float* sPart2 = sPart1 + 16 * SPW;

    const int tid  = threadIdx.x;
    const int w    = tid >> 5;          // warp 0..15: k slice [64w, 64w+64)
    const int lane = tid & 31;
    const int grp  = blockIdx.x >> 5;   // 0..3
    const int rank = blockIdx.x & 31;   // 0..31
    const int o0   = rank * 32;
    const int b0   = grp * 8;

    // ---- fill weight planes with Wh (hi/lo split) ----
    const float4* Wh4 = (const float4*)Wh;
    for (int i = tid; i < 8192; i += 512) {
        int r = i >> 8, c4 = i & 255;
        float4 v = Wh4[(o0 + r) * 256 + c4];
        __nv_bfloat16 h0 = __float2bfloat16(v.x);
        __nv_bfloat16 h1 = __float2bfloat16(v.y);
        __nv_bfloat16 h2 = __float2bfloat16(v.z);
        __nv_bfloat16 h3 = __float2bfloat16(v.w);
        char* dh = smem + OFF_WHI + r * SROW + c4 * 8;
        char* dl = smem + OFF_WLO + r * SROW + c4 * 8;
        *(__nv_bfloat162*)(dh)     = __halves2bfloat162(h0, h1);
        *(__nv_bfloat162*)(dh + 4) = __halves2bfloat162(h2, h3);
        *(__nv_bfloat162*)(dl)     = __halves2bfloat162(
            __float2bfloat16(v.x - __bfloat162float(h0)),
            __float2bfloat16(v.y - __bfloat162float(h1)));
        *(__nv_bfloat162*)(dl + 4) = __halves2bfloat162(
            __float2bfloat16(v.z - __bfloat162float(h2)),
            __float2bfloat16(v.w - __bfloat162float(h3)));
    }
    __syncthreads();

    // ---- Wh frags -> registers (resident) ----
    const uint32_t aBase = sb + (lane & 15) * SROW + (lane >> 4) * 16 + w * 128;
    uint32_t aHi[2][4][4], aLo[2][4][4];
#pragma unroll
    for (int mt = 0; mt < 2; mt++)
#pragma unroll
        for (int ks = 0; ks < 4; ks++) {
            ldsm_x4(aHi[mt][ks], aBase + OFF_WHI + mt * 16 * SROW + ks * 32);
            ldsm_x4(aLo[mt][ks], aBase + OFF_WLO + mt * 16 * SROW + ks * 32);
        }
    __syncthreads();

    // ---- overwrite planes with Wo (same layout), ldsm'd per step ----
    const float4* Wo4 = (const float4*)Wo;
    for (int i = tid; i < 8192; i += 512) {
        int r = i >> 8, c4 = i & 255;
        float4 v = Wo4[(o0 + r) * 256 + c4];
        __nv_bfloat16 h0 = __float2bfloat16(v.x);
        __nv_bfloat16 h1 = __float2bfloat16(v.y);
        __nv_bfloat16 h2 = __float2bfloat16(v.z);
        __nv_bfloat16 h3 = __float2bfloat16(v.w);
        char* dh = smem + OFF_WHI + r * SROW + c4 * 8;
        char* dl = smem + OFF_WLO + r * SROW + c4 * 8;
        *(__nv_bfloat162*)(dh)     = __halves2bfloat162(h0, h1);
        *(__nv_bfloat162*)(dh + 4) = __halves2bfloat162(h2, h3);
        *(__nv_bfloat162*)(dl)     = __halves2bfloat162(
            __float2bfloat16(v.x - __bfloat162float(h0)),
            __float2bfloat16(v.y - __bfloat162float(h1)));
        *(__nv_bfloat162*)(dl + 4) = __halves2bfloat162(
            __float2bfloat16(v.z - __bfloat162float(h2)),
            __float2bfloat16(v.w - __bfloat162float(h3)));
    }
    __syncthreads();

    // reduce mapping: out = o_local*8 + b_local, 2 threads per output
    const int out   = tid >> 1;          // 0..255
    const int halfq = tid & 1;
    const int ol    = out >> 3;          // 0..31
    const int bl    = out & 7;           // 0..7
    const size_t hrow = (size_t)(b0 + bl) * STEPS;

    float xv  = (halfq == 0) ? xproj[(hrow + 0) * HD + o0 + ol] : 0.f;
    float bov = (halfq == 0) ? bo[o0 + ol] : 0.f;

    // producer exchange addresses (parity 0/1), fragment-order layout
    uint8_t *pex0 = 0, *pex1 = 0;
    {
        int kg = o0 + ol;
        int g  = kg >> 4;
        int j  = (kg & 15) >> 1;
        int p  = 2 * (j & 3) + (j >> 2);
        int off = g * 512 + bl * 64 + p * 8;
        pex0 = g_ex[0][grp] + off;
        pex1 = g_ex[1][grp] + off;
    }
    const int coff = (4 * w) * 512 + (lane >> 2) * 64 + (lane & 3) * 16;

    uint4 vf0, vf1, vf2, vf3;    // h frags of step s-1 (persistent)

    for (int s = 0; s <= STEPS; s++) {
        // ================= merged MMA block =================
        float acc1[2][4], acc2[2][4];
#pragma unroll
        for (int mt = 0; mt < 2; mt++)
#pragma unroll
            for (int e = 0; e < 4; e++) { acc1[mt][e] = 0.f; acc2[mt][e] = 0.f; }

        if (s > 0) {
            if (s < STEPS) {
                // Wh MMAs (critical path: feeds publish)
#pragma unroll
                for (int mt = 0; mt < 2; mt++) {
                    mma_bf16_2(acc1[mt], aHi[mt][0], vf0.x, vf0.z);
                    mma_bf16_2(acc1[mt], aHi[mt][0], vf0.y, vf0.w);
                    mma_bf16_2(acc1[mt], aLo[mt][0], vf0.x, vf0.z);
                    mma_bf16_2(acc1[mt], aHi[mt][1], vf1.x, vf1.z);
                    mma_bf16_2(acc1[mt], aHi[mt][1], vf1.y, vf1.w);
                    mma_bf16_2(acc1[mt], aLo[mt][1], vf1.x, vf1.z);
                    mma_bf16_2(acc1[mt], aHi[mt][2], vf2.x, vf2.z);
                    mma_bf16_2(acc1[mt], aHi[mt][2], vf2.y, vf2.w);
                    mma_bf16_2(acc1[mt], aLo[mt][2], vf2.x, vf2.z);
                    mma_bf16_2(acc1[mt], aHi[mt][3], vf3.x, vf3.z);
                    mma_bf16_2(acc1[mt], aHi[mt][3], vf3.y, vf3.w);
                    mma_bf16_2(acc1[mt], aLo[mt][3], vf3.x, vf3.z);
                }
            }
            // Wo MMAs on the same frags
#pragma unroll
            for (int mt = 0; mt < 2; mt++) {
#pragma unroll
                for (int ks = 0; ks < 4; ks++) {
                    uint32_t oh[4], olo[4];
                    ldsm_x4(oh,  aBase + OFF_WHI + mt * 16 * SROW + ks * 32);
                    ldsm_x4(olo, aBase + OFF_WLO + mt * 16 * SROW + ks * 32);
                    uint4 vv = (ks == 0) ? vf0 : (ks == 1) ? vf1 : (ks == 2) ? vf2 : vf3;
                    mma_bf16_2(acc2[mt], oh,  vv.x, vv.z);
                    mma_bf16_2(acc2[mt], oh,  vv.y, vv.w);
                    mma_bf16_2(acc2[mt], olo, vv.x, vv.z);
                }
            }
        }

        // ---- spill both accumulator sets (one round) ----
        {
            float* pw1 = sPart1 + w * SPW;
            float* pw2 = sPart2 + w * SPW;
#pragma unroll
            for (int mt = 0; mt < 2; mt++)
#pragma unroll
                for (int e = 0; e < 4; e++) {
                    int o = mt * 16 + (lane >> 2) + ((e >> 1) << 3);
                    int b = (lane & 3) * 2 + (e & 1);
                    if (s < STEPS) pw1[o * 8 + b] = acc1[mt][e];
                    if (s > 0)     pw2[o * 8 + b] = acc2[mt][e];
                }
        }
        __syncthreads();                               // sync A

        // ---- reduce plane1 -> gelu -> publish (earliest possible) ----
        float hval = 0.f;
        if (s < STEPS) {
            float v = 0.f;
#pragma unroll
            for (int q = 0; q < 8; q++)
                v += sPart1[(halfq * 8 + q) * SPW + out];
            v += __shfl_xor_sync(0xFFFFFFFFu, v, 1);

            uint32_t bhu = 0, bbu = 0;
            if (halfq == 0) {
                v += xv;
                hval = gelu_exact(v);
                __nv_bfloat16 bh = __float2bfloat16(hval);
                __nv_bfloat16 bb = __float2bfloat16(hval - __bfloat162float(bh));
                bhu = *(unsigned short*)&bh;
                bbu = *(unsigned short*)&bb;
            }
            uint32_t obh = __shfl_xor_sync(0xFFFFFFFFu, bhu, 16);
            uint32_t obb = __shfl_xor_sync(0xFFFFFFFFu, bbu, 16);
            if (halfq == 0 && (tid & 16) == 0) {
                unsigned long long val =
                    (unsigned long long)(bhu | (obh << 16)) |
                    ((unsigned long long)(bbu | (obb << 16)) << 32);
                *(unsigned long long*)((s & 1) ? pex1 : pex0) = val;
            }
        }
        __syncthreads();                               // sync B (publish visible)

        if (s < STEPS) {
            if (tid == 0)
                asm volatile("red.release.gpu.global.add.u32 [%0], %1;"
                             :: "l"(&g_bar2[grp][s]), "r"(1u) : "memory");
            if (halfq == 0)
                hidden[(hrow + s) * HD + o0 + ol] = hval;

            float xnext = 0.f;
            if (halfq == 0 && s + 1 < STEPS)
                xnext = xproj[(hrow + s + 1) * HD + o0 + ol];

            if (tid == 0) {
                unsigned int cnt;
                do {
                    asm volatile("ld.acquire.gpu.global.u32 %0, [%1];"
                                 : "=r"(cnt) : "l"(&g_bar2[grp][s]) : "memory");
                } while (cnt < GRP_CTAS);
            }
            __syncthreads();                           // sync C (h_s available)

            // prefetch h_s frags NOW; epilogue work below hides the latency
            const uint8_t* exr = g_ex[s & 1][grp] + coff;
            vf0 = __ldcg((const uint4*)(exr + 0 * 512));
            vf1 = __ldcg((const uint4*)(exr + 1 * 512));
            vf2 = __ldcg((const uint4*)(exr + 2 * 512));
            vf3 = __ldcg((const uint4*)(exr + 3 * 512));
            xv = xnext;
        }

        // ---- reduce plane2 -> outproj row s-1 (overlaps frag LDGs) ----
        if (s > 0) {
            float v2 = 0.f;
#pragma unroll
            for (int q = 0; q < 8; q++)
                v2 += sPart2[(halfq * 8 + q) * SPW + out];
            v2 += __shfl_xor_sync(0xFFFFFFFFu, v2, 1);
            if (halfq == 0)
                outproj[(hrow + s - 1) * HD + o0 + ol] = v2 + bov;
        }
        __syncthreads();                               // sync D (protect planes)
    }
}

// =================================================================
extern "C" void kernel_launch(void* const* d_in, const int* in_sizes, int n_in,
                              void* d_out, int out_size) {
    const float* seq = (const float*)d_in[0];   // (B,T,D)
    const float* Wi  = (const float*)d_in[1];   // (H,D)
    const float* bi  = (const float*)d_in[2];   // (H,)
    const float* Wh  = (const float*)d_in[3];   // (H,H)
    const float* Wo  = (const float*)d_in[4];   // (H,H)
    const float* bo  = (const float*)d_in[5];   // (H,)

    float* out     = (float*)d_out;
    float* hidden  = out;                          // (B,T,H)
    float* outproj = out + (size_t)BT * HD;        // (B,T,H)

    void *xp_addr = 0, *bar_addr = 0, *ahi = 0, *alo = 0, *bhi = 0, *blo = 0;
    cudaGetSymbolAddress(&xp_addr, g_xproj);
    cudaGetSymbolAddress(&bar_addr, g_bar2);
    cudaGetSymbolAddress(&ahi, g_Ahi);
    cudaGetSymbolAddress(&alo, g_Alo);
    cudaGetSymbolAddress(&bhi, g_Bhi);
    cudaGetSymbolAddress(&blo, g_Blo);

    cudaMemsetAsync(bar_addr, 0, 4 * STEPS * sizeof(unsigned int));

    const int nA4 = BT * HD / 4;       // 8388608
    const int nW4 = HD * HD / 4;       // 262144
    const int gemm_smem = GSTAGES * STAGE_B;   // 122880
    cudaFuncSetAttribute(mma_gemm, cudaFuncAttributeMaxDynamicSharedMemorySize, gemm_smem);
    dim3 ggrid(HD / 128, BT / 128);    // (8, 256)

    // 1) input projection: xproj = seq @ Wi^T + bi  (split-bf16 HMMA)
    split_bf16<<<nA4 / 256, 256>>>(seq, (__nv_bfloat16*)ahi, (__nv_bfloat16*)alo, nA4);
    split_bf16<<<nW4 / 256, 256>>>(Wi, (__nv_bfloat16*)bhi, (__nv_bfloat16*)blo, nW4);
    mma_gemm<<<ggrid, 256, gemm_smem>>>((const __nv_bfloat16*)ahi, (const __nv_bfloat16*)alo,
                                        (const __nv_bfloat16*)bhi, (const __nv_bfloat16*)blo,
                                        bi, (float*)xp_addr);

    // 2) recurrent scan + fused output projection
    cudaFuncSetAttribute(scan_kernel, cudaFuncAttributeMaxDynamicSharedMemorySize, SCAN_SMEM);
    scan_kernel<<<NCTA, 512, SCAN_SMEM>>>((const float*)xp_addr, Wh, Wo, bo,
                                          hidden, outproj);
}

// round 15
// speedup vs baseline: 1.0834x; 1.0834x over previous
#include <cuda_runtime.h>
#include <cuda_bf16.h>
#include <math.h>
#include <stdint.h>

// Problem dims (fixed by the dataset)
#define BATCH   32
#define STEPS   1024      // T
#define HD      1024      // D == H
#define BT      32768     // BATCH*STEPS rows
#define NCTA    128       // scan grid: 4 groups x 32 CTAs
#define GRP_CTAS 32

// ---------------- scratch (no allocations allowed) ----------------
__device__ float         g_xproj[(size_t)BT * HD];     // 128 MB input-proj result
__device__ unsigned int  g_bar2[4][STEPS];             // per-group per-step barrier counters
__device__ __nv_bfloat16 g_Ahi[(size_t)BT * HD];       // 64 MB (seq split)
__device__ __nv_bfloat16 g_Alo[(size_t)BT * HD];       // 64 MB
__device__ __nv_bfloat16 g_Bhi[HD * HD];               // 2 MB
__device__ __nv_bfloat16 g_Blo[HD * HD];               // 2 MB
// fragment-order h exchange: [parity][grp] -> 64 k-groups x 8 b x 64 B
__device__ uint8_t       g_ex[2][4][64 * 8 * 64];      // 256 KB total

// =================================================================
// helpers (plain sm_80-era PTX only)
// =================================================================
__device__ __forceinline__ uint32_t smem_u32(const void* p) {
    uint32_t a;
    asm("{ .reg .u64 t; cvta.to.shared.u64 t, %1; cvt.u32.u64 %0, t; }" : "=r"(a) : "l"(p));
    return a;
}
__device__ __forceinline__ void cp_async16(uint32_t dst, const void* src) {
    asm volatile("cp.async.cg.shared.global [%0], [%1], 16;" :: "r"(dst), "l"(src));
}
__device__ __forceinline__ void cp_commit() {
    asm volatile("cp.async.commit_group;");
}
__device__ __forceinline__ void cp_wait1() {
    asm volatile("cp.async.wait_group 1;");
}
__device__ __forceinline__ void ldsm_x4(uint32_t* r, uint32_t addr) {
    asm volatile("ldmatrix.sync.aligned.m8n8.x4.shared.b16 {%0,%1,%2,%3}, [%4];"
                 : "=r"(r[0]), "=r"(r[1]), "=r"(r[2]), "=r"(r[3]) : "r"(addr));
}
__device__ __forceinline__ void mma_bf16(float* c, const uint32_t* a, const uint32_t* b) {
    asm volatile(
        "mma.sync.aligned.m16n8k16.row.col.f32.bf16.bf16.f32 "
        "{%0,%1,%2,%3}, {%4,%5,%6,%7}, {%8,%9}, {%0,%1,%2,%3};"
        : "+f"(c[0]), "+f"(c[1]), "+f"(c[2]), "+f"(c[3])
        : "r"(a[0]), "r"(a[1]), "r"(a[2]), "r"(a[3]), "r"(b[0]), "r"(b[1]));
}
__device__ __forceinline__ void mma_bf16_2(float* c, const uint32_t* a,
                                           uint32_t b0, uint32_t b1) {
    asm volatile(
        "mma.sync.aligned.m16n8k16.row.col.f32.bf16.bf16.f32 "
        "{%0,%1,%2,%3}, {%4,%5,%6,%7}, {%8,%9}, {%0,%1,%2,%3};"
        : "+f"(c[0]), "+f"(c[1]), "+f"(c[2]), "+f"(c[3])
        : "r"(a[0]), "r"(a[1]), "r"(a[2]), "r"(a[3]), "r"(b0), "r"(b1));
}

// =================================================================
// split fp32 -> bf16 hi + bf16 lo
// =================================================================
__global__ void split_bf16(const float* __restrict__ in,
                           __nv_bfloat16* __restrict__ hi,
                           __nv_bfloat16* __restrict__ lo, int n4) {
    int i = blockIdx.x * blockDim.x + threadIdx.x;
    if (i >= n4) return;
    float4 v = ((const float4*)in)[i];
    __nv_bfloat16 h0 = __float2bfloat16(v.x);
    __nv_bfloat16 h1 = __float2bfloat16(v.y);
    __nv_bfloat16 h2 = __float2bfloat16(v.z);
    __nv_bfloat16 h3 = __float2bfloat16(v.w);
    __nv_bfloat16 l0 = __float2bfloat16(v.x - __bfloat162float(h0));
    __nv_bfloat16 l1 = __float2bfloat16(v.y - __bfloat162float(h1));
    __nv_bfloat16 l2 = __float2bfloat16(v.z - __bfloat162float(h2));
    __nv_bfloat16 l3 = __float2bfloat16(v.w - __bfloat162float(h3));
    ((__nv_bfloat162*)hi)[2 * i + 0] = __halves2bfloat162(h0, h1);
    ((__nv_bfloat162*)hi)[2 * i + 1] = __halves2bfloat162(h2, h3);
    ((__nv_bfloat162*)lo)[2 * i + 0] = __halves2bfloat162(l0, l1);
    ((__nv_bfloat162*)lo)[2 * i + 1] = __halves2bfloat162(l2, l3);
}

// =================================================================
// HMMA split-bf16 GEMM (NT)  -- unchanged (passing since R4)
// =================================================================
#define GSTAGES 3
#define TILE_B   10240
#define STAGE_B  (4 * TILE_B)
#define ROWB     80

__global__ __launch_bounds__(256)
void mma_gemm(const __nv_bfloat16* __restrict__ Ahi, const __nv_bfloat16* __restrict__ Alo,
              const __nv_bfloat16* __restrict__ Bhi, const __nv_bfloat16* __restrict__ Blo,
              const float* __restrict__ bias, float* __restrict__ C) {
    extern __shared__ char dsm[];
    const uint32_t sb = smem_u32(dsm);

    const int tid = threadIdx.x;
    const int wid = tid >> 5;
    const int lane = tid & 31;
    const int bm = blockIdx.y * 128;
    const int bn = blockIdx.x * 128;
    const int wm = (wid >> 2) * 64;
    const int wn = (wid & 3) * 32;

    const int lt  = tid >> 6;
    const int lid = tid & 63;
    const __nv_bfloat16* lsrc = (lt == 0) ? Ahi : (lt == 1) ? Alo : (lt == 2) ? Bhi : Blo;
    const int lrowb = (lt < 2) ? bm : bn;

    float acc[4][4][4];
#pragma unroll
    for (int i = 0; i < 4; i++)
#pragma unroll
        for (int j = 0; j < 4; j++)
#pragma unroll
            for (int e = 0; e < 4; e++) acc[i][j][e] = 0.f;

#pragma unroll
    for (int ps = 0; ps < GSTAGES - 1; ps++) {
        uint32_t dstb = sb + ps * STAGE_B + lt * TILE_B;
#pragma unroll
        for (int i = 0; i < 8; i++) {
            int idx = i * 64 + lid;
            int r = idx >> 2, c = idx & 3;
            cp_async16(dstb + r * ROWB + c * 16,
                       lsrc + (size_t)(lrowb + r) * HD + ps * 32 + c * 8);
        }
        cp_commit();
    }

    for (int kt = 0; kt < HD / 32; kt++) {
        cp_wait1();
        __syncthreads();

        if (kt + GSTAGES - 1 < HD / 32) {
            uint32_t dstb = sb + ((kt + GSTAGES - 1) % GSTAGES) * STAGE_B + lt * TILE_B;
#pragma unroll
            for (int i = 0; i < 8; i++) {
                int idx = i * 64 + lid;
                int r = idx >> 2, c = idx & 3;
                cp_async16(dstb + r * ROWB + c * 16,
                           lsrc + (size_t)(lrowb + r) * HD + (kt + GSTAGES - 1) * 32 + c * 8);
            }
        }
        cp_commit();

        uint32_t stg = sb + (kt % GSTAGES) * STAGE_B;
        uint32_t aBaseH = stg + 0 * TILE_B;
        uint32_t aBaseL = stg + 1 * TILE_B;
        uint32_t bBaseH = stg + 2 * TILE_B;
        uint32_t bBaseL = stg + 3 * TILE_B;

#pragma unroll
        for (int ks = 0; ks < 2; ks++) {
            uint32_t ah[4][4], al[4][4], bh[4][2], bl[4][2];
            int arow = (lane & 15);
            int acol = (lane >> 4) * 16 + ks * 32;
#pragma unroll
            for (int mt = 0; mt < 4; mt++) {
                ldsm_x4(ah[mt], aBaseH + (wm + mt * 16 + arow) * ROWB + acol);
                ldsm_x4(al[mt], aBaseL + (wm + mt * 16 + arow) * ROWB + acol);
            }
            int brow = ((lane >> 4) << 3) + (lane & 7);
            int bcol = ((lane >> 3) & 1) * 16 + ks * 32;
#pragma unroll
            for (int p = 0; p < 2; p++) {
                uint32_t t[4];
                ldsm_x4(t, bBaseH + (wn + p * 16 + brow) * ROWB + bcol);
                bh[2 * p][0] = t[0]; bh[2 * p][1] = t[1];
                bh[2 * p + 1][0] = t[2]; bh[2 * p + 1][1] = t[3];
                ldsm_x4(t, bBaseL + (wn + p * 16 + brow) * ROWB + bcol);
                bl[2 * p][0] = t[0]; bl[2 * p][1] = t[1];
                bl[2 * p + 1][0] = t[2]; bl[2 * p + 1][1] = t[3];
            }
#pragma unroll
            for (int mt = 0; mt < 4; mt++)
#pragma unroll
                for (int nt = 0; nt < 4; nt++) {
                    mma_bf16(acc[mt][nt], ah[mt], bh[nt]);
                    mma_bf16(acc[mt][nt], ah[mt], bl[nt]);
                    mma_bf16(acc[mt][nt], al[mt], bh[nt]);
                }
        }
    }

#pragma unroll
    for (int mt = 0; mt < 4; mt++) {
#pragma unroll
        for (int nt = 0; nt < 4; nt++) {
            int m0 = bm + wm + mt * 16 + (lane >> 2);
            int n0 = bn + wn + nt * 8 + (lane & 3) * 2;
            float b0 = bias[n0], b1 = bias[n0 + 1];
            float2 v0 = make_float2(acc[mt][nt][0] + b0, acc[mt][nt][1] + b1);
            float2 v1 = make_float2(acc[mt][nt][2] + b0, acc[mt][nt][3] + b1);
            *(float2*)&C[(size_t)m0 * HD + n0] = v0;
            *(float2*)&C[(size_t)(m0 + 8) * HD + n0] = v1;
        }
    }
}

// =================================================================
// Persistent recurrent scan v9 (R11 ordering + early poll + hidden frag LDG):
//  phase1: Wh MMA -> reduce1 -> gelu -> publish -> release   (critical path)
//  phase2: Wo MMA + spill (barrier shadow) -> poll -> frag prefetch ->
//          reduce2 + outproj store (hides frag LDG latency)
// =================================================================
__device__ __forceinline__ float gelu_exact(float x) {
    return 0.5f * x * (1.0f + erff(x * 0.70710678118654752f));
}

#define SROW       2064      // padded weight smem row (1032 bf16)
#define OFF_WHI    0
#define OFF_WLO    66048     // 32*2064
#define OFF_PART   132096
#define SPW        264       // floats per warp partial row
#define SCAN_SMEM  (OFF_PART + 16 * SPW * 4)   // 148992 B

__global__ __launch_bounds__(512)
void scan_kernel(const float* __restrict__ xproj,
                 const float* __restrict__ Wh,
                 const float* __restrict__ Wo,
                 const float* __restrict__ bo,
                 float* __restrict__ hidden,
                 float* __restrict__ outproj) {
    extern __shared__ char smem[];
    const uint32_t sb = smem_u32(smem);
    float* sPart = (float*)(smem + OFF_PART);

    const int tid  = threadIdx.x;
    const int w    = tid >> 5;          // warp 0..15: k slice [64w, 64w+64)
    const int lane = tid & 31;
    const int grp  = blockIdx.x >> 5;   // 0..3
    const int rank = blockIdx.x & 31;   // 0..31
    const int o0   = rank * 32;
    const int b0   = grp * 8;

    // ---- fill weight planes with Wh (hi/lo split) ----
    const float4* Wh4 = (const float4*)Wh;
    for (int i = tid; i < 8192; i += 512) {
        int r = i >> 8, c4 = i & 255;
        float4 v = Wh4[(o0 + r) * 256 + c4];
        __nv_bfloat16 h0 = __float2bfloat16(v.x);
        __nv_bfloat16 h1 = __float2bfloat16(v.y);
        __nv_bfloat16 h2 = __float2bfloat16(v.z);
        __nv_bfloat16 h3 = __float2bfloat16(v.w);
        char* dh = smem + OFF_WHI + r * SROW + c4 * 8;
        char* dl = smem + OFF_WLO + r * SROW + c4 * 8;
        *(__nv_bfloat162*)(dh)     = __halves2bfloat162(h0, h1);
        *(__nv_bfloat162*)(dh + 4) = __halves2bfloat162(h2, h3);
        *(__nv_bfloat162*)(dl)     = __halves2bfloat162(
            __float2bfloat16(v.x - __bfloat162float(h0)),
            __float2bfloat16(v.y - __bfloat162float(h1)));
        *(__nv_bfloat162*)(dl + 4) = __halves2bfloat162(
            __float2bfloat16(v.z - __bfloat162float(h2)),
            __float2bfloat16(v.w - __bfloat162float(h3)));
    }
    __syncthreads();

    // ---- Wh frags -> registers (resident) ----
    const uint32_t aBase = sb + (lane & 15) * SROW + (lane >> 4) * 16 + w * 128;
    uint32_t aHi[2][4][4], aLo[2][4][4];
#pragma unroll
    for (int mt = 0; mt < 2; mt++)
#pragma unroll
        for (int ks = 0; ks < 4; ks++) {
            ldsm_x4(aHi[mt][ks], aBase + OFF_WHI + mt * 16 * SROW + ks * 32);
            ldsm_x4(aLo[mt][ks], aBase + OFF_WLO + mt * 16 * SROW + ks * 32);
        }
    __syncthreads();

    // ---- overwrite planes with Wo (same layout), ldsm'd per step ----
    const float4* Wo4 = (const float4*)Wo;
    for (int i = tid; i < 8192; i += 512) {
        int r = i >> 8, c4 = i & 255;
        float4 v = Wo4[(o0 + r) * 256 + c4];
        __nv_bfloat16 h0 = __float2bfloat16(v.x);
        __nv_bfloat16 h1 = __float2bfloat16(v.y);
        __nv_bfloat16 h2 = __float2bfloat16(v.z);
        __nv_bfloat16 h3 = __float2bfloat16(v.w);
        char* dh = smem + OFF_WHI + r * SROW + c4 * 8;
        char* dl = smem + OFF_WLO + r * SROW + c4 * 8;
        *(__nv_bfloat162*)(dh)     = __halves2bfloat162(h0, h1);
        *(__nv_bfloat162*)(dh + 4) = __halves2bfloat162(h2, h3);
        *(__nv_bfloat162*)(dl)     = __halves2bfloat162(
            __float2bfloat16(v.x - __bfloat162float(h0)),
            __float2bfloat16(v.y - __bfloat162float(h1)));
        *(__nv_bfloat162*)(dl + 4) = __halves2bfloat162(
            __float2bfloat16(v.z - __bfloat162float(h2)),
            __float2bfloat16(v.w - __bfloat162float(h3)));
    }
    __syncthreads();

    // reduce mapping: out = o_local*8 + b_local, 2 threads per output
    const int out   = tid >> 1;          // 0..255
    const int halfq = tid & 1;
    const int ol    = out >> 3;          // 0..31
    const int bl    = out & 7;           // 0..7
    const size_t hrow = (size_t)(b0 + bl) * STEPS;

    float xv  = (halfq == 0) ? xproj[(hrow + 0) * HD + o0 + ol] : 0.f;
    float bov = (halfq == 0) ? bo[o0 + ol] : 0.f;

    // producer exchange addresses (parity 0/1), fragment-order layout
    uint8_t *pex0 = 0, *pex1 = 0;
    {
        int kg = o0 + ol;
        int g  = kg >> 4;
        int j  = (kg & 15) >> 1;
        int p  = 2 * (j & 3) + (j >> 2);
        int off = g * 512 + bl * 64 + p * 8;
        pex0 = g_ex[0][grp] + off;
        pex1 = g_ex[1][grp] + off;
    }
    const int coff = (4 * w) * 512 + (lane >> 2) * 64 + (lane & 3) * 16;

    uint4 vf0, vf1, vf2, vf3;    // h frags of step s-1 (persistent)

    for (int s = 0; s <= STEPS; s++) {
        float hval = 0.f;
        float xnext = 0.f;

        // ================= phase1: Wh path (critical) =================
        if (s < STEPS) {
            float acc[2][4];
#pragma unroll
            for (int mt = 0; mt < 2; mt++)
#pragma unroll
                for (int e = 0; e < 4; e++) acc[mt][e] = 0.f;

            if (s > 0) {
#pragma unroll
                for (int mt = 0; mt < 2; mt++) {
                    mma_bf16_2(acc[mt], aHi[mt][0], vf0.x, vf0.z);
                    mma_bf16_2(acc[mt], aHi[mt][0], vf0.y, vf0.w);
                    mma_bf16_2(acc[mt], aLo[mt][0], vf0.x, vf0.z);
                    mma_bf16_2(acc[mt], aHi[mt][1], vf1.x, vf1.z);
                    mma_bf16_2(acc[mt], aHi[mt][1], vf1.y, vf1.w);
                    mma_bf16_2(acc[mt], aLo[mt][1], vf1.x, vf1.z);
                    mma_bf16_2(acc[mt], aHi[mt][2], vf2.x, vf2.z);
                    mma_bf16_2(acc[mt], aHi[mt][2], vf2.y, vf2.w);
                    mma_bf16_2(acc[mt], aLo[mt][2], vf2.x, vf2.z);
                    mma_bf16_2(acc[mt], aHi[mt][3], vf3.x, vf3.z);
                    mma_bf16_2(acc[mt], aHi[mt][3], vf3.y, vf3.w);
                    mma_bf16_2(acc[mt], aLo[mt][3], vf3.x, vf3.z);
                }
            }
            {
                float* pw = sPart + w * SPW;
#pragma unroll
                for (int mt = 0; mt < 2; mt++)
#pragma unroll
                    for (int e = 0; e < 4; e++) {
                        int o = mt * 16 + (lane >> 2) + ((e >> 1) << 3);
                        int b = (lane & 3) * 2 + (e & 1);
                        pw[o * 8 + b] = acc[mt][e];
                    }
            }
            __syncthreads();                           // sync A

            float v = 0.f;
#pragma unroll
            for (int q = 0; q < 8; q++)
                v += sPart[(halfq * 8 + q) * SPW + out];
            v += __shfl_xor_sync(0xFFFFFFFFu, v, 1);

            uint32_t bhu = 0, bbu = 0;
            if (halfq == 0) {
                v += xv;
                hval = gelu_exact(v);
                __nv_bfloat16 bh = __float2bfloat16(hval);
                __nv_bfloat16 bb = __float2bfloat16(hval - __bfloat162float(bh));
                bhu = *(unsigned short*)&bh;
                bbu = *(unsigned short*)&bb;
            }
            uint32_t obh = __shfl_xor_sync(0xFFFFFFFFu, bhu, 16);
            uint32_t obb = __shfl_xor_sync(0xFFFFFFFFu, bbu, 16);
            if (halfq == 0 && (tid & 16) == 0) {
                unsigned long long val =
                    (unsigned long long)(bhu | (obh << 16)) |
                    ((unsigned long long)(bbu | (obb << 16)) << 32);
                *(unsigned long long*)((s & 1) ? pex1 : pex0) = val;
            }
            __syncthreads();                           // sync B (publish visible)

            if (tid == 0)
                asm volatile("red.release.gpu.global.add.u32 [%0], %1;"
                             :: "l"(&g_bar2[grp][s]), "r"(1u) : "memory");
            if (halfq == 0) {
                hidden[(hrow + s) * HD + o0 + ol] = hval;
                if (s + 1 < STEPS)
                    xnext = xproj[(hrow + s + 1) * HD + o0 + ol];
            }
        }

        // ========== phase2: Wo MMA + spill (barrier shadow) ==========
        if (s > 0) {
            float acc2[2][4];
#pragma unroll
            for (int mt = 0; mt < 2; mt++)
#pragma unroll
                for (int e = 0; e < 4; e++) acc2[mt][e] = 0.f;
#pragma unroll
            for (int mt = 0; mt < 2; mt++) {
#pragma unroll
                for (int ks = 0; ks < 4; ks++) {
                    uint32_t oh[4], olo[4];
                    ldsm_x4(oh,  aBase + OFF_WHI + mt * 16 * SROW + ks * 32);
                    ldsm_x4(olo, aBase + OFF_WLO + mt * 16 * SROW + ks * 32);
                    uint4 vv = (ks == 0) ? vf0 : (ks == 1) ? vf1 : (ks == 2) ? vf2 : vf3;
                    mma_bf16_2(acc2[mt], oh,  vv.x, vv.z);
                    mma_bf16_2(acc2[mt], oh,  vv.y, vv.w);
                    mma_bf16_2(acc2[mt], olo, vv.x, vv.z);
                }
            }
            {
                float* pw = sPart + w * SPW;   // plane free after sync B
#pragma unroll
                for (int mt = 0; mt < 2; mt++)
#pragma unroll
                    for (int e = 0; e < 4; e++) {
                        int o = mt * 16 + (lane >> 2) + ((e >> 1) << 3);
                        int b = (lane & 3) * 2 + (e & 1);
                        pw[o * 8 + b] = acc2[mt][e];
                    }
            }
        }

        // ========== poll (overlaps other warps' spill2 drain) ==========
        if (s < STEPS && tid == 0) {
            unsigned int cnt;
            do {
                asm volatile("ld.acquire.gpu.global.u32 %0, [%1];"
                             : "=r"(cnt) : "l"(&g_bar2[grp][s]) : "memory");
            } while (cnt < GRP_CTAS);
        }
        __syncthreads();                               // sync C (h_s + spill2 ready)

        // ---- prefetch h_s frags immediately; work below hides latency ----
        if (s < STEPS) {
            const uint8_t* exr = g_ex[s & 1][grp] + coff;
            vf0 = __ldcg((const uint4*)(exr + 0 * 512));
            vf1 = __ldcg((const uint4*)(exr + 1 * 512));
            vf2 = __ldcg((const uint4*)(exr + 2 * 512));
            vf3 = __ldcg((const uint4*)(exr + 3 * 512));
            xv = xnext;
        }

        // ---- reduce plane -> outproj row s-1 (under frag LDG shadow) ----
        if (s > 0) {
            float v2 = 0.f;
#pragma unroll
            for (int q = 0; q < 8; q++)
                v2 += sPart[(halfq * 8 + q) * SPW + out];
            v2 += __shfl_xor_sync(0xFFFFFFFFu, v2, 1);
            if (halfq == 0)
                outproj[(hrow + s - 1) * HD + o0 + ol] = v2 + bov;
        }
        __syncthreads();                               // sync D (plane free)
    }
}

// =================================================================
extern "C" void kernel_launch(void* const* d_in, const int* in_sizes, int n_in,
                              void* d_out, int out_size) {
    const float* seq = (const float*)d_in[0];   // (B,T,D)
    const float* Wi  = (const float*)d_in[1];   // (H,D)
    const float* bi  = (const float*)d_in[2];   // (H,)
    const float* Wh  = (const float*)d_in[3];   // (H,H)
    const float* Wo  = (const float*)d_in[4];   // (H,H)
    const float* bo  = (const float*)d_in[5];   // (H,)

    float* out     = (float*)d_out;
    float* hidden  = out;                          // (B,T,H)
    float* outproj = out + (size_t)BT * HD;        // (B,T,H)

    void *xp_addr = 0, *bar_addr = 0, *ahi = 0, *alo = 0, *bhi = 0, *blo = 0;
    cudaGetSymbolAddress(&xp_addr, g_xproj);
    cudaGetSymbolAddress(&bar_addr, g_bar2);
    cudaGetSymbolAddress(&ahi, g_Ahi);
    cudaGetSymbolAddress(&alo, g_Alo);
    cudaGetSymbolAddress(&bhi, g_Bhi);
    cudaGetSymbolAddress(&blo, g_Blo);

    cudaMemsetAsync(bar_addr, 0, 4 * STEPS * sizeof(unsigned int));

    const int nA4 = BT * HD / 4;       // 8388608
    const int nW4 = HD * HD / 4;       // 262144
    const int gemm_smem = GSTAGES * STAGE_B;   // 122880
    cudaFuncSetAttribute(mma_gemm, cudaFuncAttributeMaxDynamicSharedMemorySize, gemm_smem);
    dim3 ggrid(HD / 128, BT / 128);    // (8, 256)

    // 1) input projection: xproj = seq @ Wi^T + bi  (split-bf16 HMMA)
    split_bf16<<<nA4 / 256, 256>>>(seq, (__nv_bfloat16*)ahi, (__nv_bfloat16*)alo, nA4);
    split_bf16<<<nW4 / 256, 256>>>(Wi, (__nv_bfloat16*)bhi, (__nv_bfloat16*)blo, nW4);
    mma_gemm<<<ggrid, 256, gemm_smem>>>((const __nv_bfloat16*)ahi, (const __nv_bfloat16*)alo,
                                        (const __nv_bfloat16*)bhi, (const __nv_bfloat16*)blo,
                                        bi, (float*)xp_addr);

    // 2) recurrent scan + fused output projection
    cudaFuncSetAttribute(scan_kernel, cudaFuncAttributeMaxDynamicSharedMemorySize, SCAN_SMEM);
    scan_kernel<<<NCTA, 512, SCAN_SMEM>>>((const float*)xp_addr, Wh, Wo, bo,
                                          hidden, outproj);
}

// round 17
// speedup vs baseline: 1.1415x; 1.0537x over previous
#include <cuda_runtime.h>
#include <cuda_bf16.h>
#include <math.h>
#include <stdint.h>

// Problem dims (fixed by the dataset)
#define BATCH   32
#define STEPS   1024      // T
#define HD      1024      // D == H
#define BT      32768     // BATCH*STEPS rows
#define NCTA    128       // scan grid: 4 groups x 32 CTAs
#define GRP_CTAS 32

// ---------------- scratch (no allocations allowed) ----------------
__device__ float         g_xproj[(size_t)BT * HD];     // 128 MB input-proj result
__device__ unsigned int  g_bar2[4][STEPS];             // per-group per-step barrier counters
__device__ __nv_bfloat16 g_Ahi[(size_t)BT * HD];       // 64 MB (seq split)
__device__ __nv_bfloat16 g_Alo[(size_t)BT * HD];       // 64 MB
__device__ __nv_bfloat16 g_Bhi[HD * HD];               // 2 MB
__device__ __nv_bfloat16 g_Blo[HD * HD];               // 2 MB
// fragment-order h exchange: [parity][grp] -> 64 k-groups x 8 b x 64 B
__device__ uint8_t       g_ex[2][4][64 * 8 * 64];      // 256 KB total

// =================================================================
// helpers (plain sm_80-era PTX only)
// =================================================================
__device__ __forceinline__ uint32_t smem_u32(const void* p) {
    uint32_t a;
    asm("{ .reg .u64 t; cvta.to.shared.u64 t, %1; cvt.u32.u64 %0, t; }" : "=r"(a) : "l"(p));
    return a;
}
__device__ __forceinline__ void cp_async16(uint32_t dst, const void* src) {
    asm volatile("cp.async.cg.shared.global [%0], [%1], 16;" :: "r"(dst), "l"(src));
}
__device__ __forceinline__ void cp_commit() {
    asm volatile("cp.async.commit_group;");
}
__device__ __forceinline__ void cp_wait1() {
    asm volatile("cp.async.wait_group 1;");
}
__device__ __forceinline__ void ldsm_x4(uint32_t* r, uint32_t addr) {
    asm volatile("ldmatrix.sync.aligned.m8n8.x4.shared.b16 {%0,%1,%2,%3}, [%4];"
                 : "=r"(r[0]), "=r"(r[1]), "=r"(r[2]), "=r"(r[3]) : "r"(addr));
}
__device__ __forceinline__ void mma_bf16(float* c, const uint32_t* a, const uint32_t* b) {
    asm volatile(
        "mma.sync.aligned.m16n8k16.row.col.f32.bf16.bf16.f32 "
        "{%0,%1,%2,%3}, {%4,%5,%6,%7}, {%8,%9}, {%0,%1,%2,%3};"
        : "+f"(c[0]), "+f"(c[1]), "+f"(c[2]), "+f"(c[3])
        : "r"(a[0]), "r"(a[1]), "r"(a[2]), "r"(a[3]), "r"(b[0]), "r"(b[1]));
}
__device__ __forceinline__ void mma_bf16_2(float* c, const uint32_t* a,
                                           uint32_t b0, uint32_t b1) {
    asm volatile(
        "mma.sync.aligned.m16n8k16.row.col.f32.bf16.bf16.f32 "
        "{%0,%1,%2,%3}, {%4,%5,%6,%7}, {%8,%9}, {%0,%1,%2,%3};"
        : "+f"(c[0]), "+f"(c[1]), "+f"(c[2]), "+f"(c[3])
        : "r"(a[0]), "r"(a[1]), "r"(a[2]), "r"(a[3]), "r"(b0), "r"(b1));
}

// =================================================================
// split fp32 -> bf16 hi + bf16 lo
// =================================================================
__global__ void split_bf16(const float* __restrict__ in,
                           __nv_bfloat16* __restrict__ hi,
                           __nv_bfloat16* __restrict__ lo, int n4) {
    int i = blockIdx.x * blockDim.x + threadIdx.x;
    if (i >= n4) return;
    float4 v = ((const float4*)in)[i];
    __nv_bfloat16 h0 = __float2bfloat16(v.x);
    __nv_bfloat16 h1 = __float2bfloat16(v.y);
    __nv_bfloat16 h2 = __float2bfloat16(v.z);
    __nv_bfloat16 h3 = __float2bfloat16(v.w);
    __nv_bfloat16 l0 = __float2bfloat16(v.x - __bfloat162float(h0));
    __nv_bfloat16 l1 = __float2bfloat16(v.y - __bfloat162float(h1));
    __nv_bfloat16 l2 = __float2bfloat16(v.z - __bfloat162float(h2));
    __nv_bfloat16 l3 = __float2bfloat16(v.w - __bfloat162float(h3));
    ((__nv_bfloat162*)hi)[2 * i + 0] = __halves2bfloat162(h0, h1);
    ((__nv_bfloat162*)hi)[2 * i + 1] = __halves2bfloat162(h2, h3);
    ((__nv_bfloat162*)lo)[2 * i + 0] = __halves2bfloat162(l0, l1);
    ((__nv_bfloat162*)lo)[2 * i + 1] = __halves2bfloat162(l2, l3);
}

// =================================================================
// HMMA split-bf16 GEMM (NT)  -- unchanged (passing since R4)
// =================================================================
#define GSTAGES 3
#define TILE_B   10240
#define STAGE_B  (4 * TILE_B)
#define ROWB     80

__global__ __launch_bounds__(256)
void mma_gemm(const __nv_bfloat16* __restrict__ Ahi, const __nv_bfloat16* __restrict__ Alo,
              const __nv_bfloat16* __restrict__ Bhi, const __nv_bfloat16* __restrict__ Blo,
              const float* __restrict__ bias, float* __restrict__ C) {
    extern __shared__ char dsm[];
    const uint32_t sb = smem_u32(dsm);

    const int tid = threadIdx.x;
    const int wid = tid >> 5;
    const int lane = tid & 31;
    const int bm = blockIdx.y * 128;
    const int bn = blockIdx.x * 128;
    const int wm = (wid >> 2) * 64;
    const int wn = (wid & 3) * 32;

    const int lt  = tid >> 6;
    const int lid = tid & 63;
    const __nv_bfloat16* lsrc = (lt == 0) ? Ahi : (lt == 1) ? Alo : (lt == 2) ? Bhi : Blo;
    const int lrowb = (lt < 2) ? bm : bn;

    float acc[4][4][4];
#pragma unroll
    for (int i = 0; i < 4; i++)
#pragma unroll
        for (int j = 0; j < 4; j++)
#pragma unroll
            for (int e = 0; e < 4; e++) acc[i][j][e] = 0.f;

#pragma unroll
    for (int ps = 0; ps < GSTAGES - 1; ps++) {
        uint32_t dstb = sb + ps * STAGE_B + lt * TILE_B;
#pragma unroll
        for (int i = 0; i < 8; i++) {
            int idx = i * 64 + lid;
            int r = idx >> 2, c = idx & 3;
            cp_async16(dstb + r * ROWB + c * 16,
                       lsrc + (size_t)(lrowb + r) * HD + ps * 32 + c * 8);
        }
        cp_commit();
    }

    for (int kt = 0; kt < HD / 32; kt++) {
        cp_wait1();
        __syncthreads();

        if (kt + GSTAGES - 1 < HD / 32) {
            uint32_t dstb = sb + ((kt + GSTAGES - 1) % GSTAGES) * STAGE_B + lt * TILE_B;
#pragma unroll
            for (int i = 0; i < 8; i++) {
                int idx = i * 64 + lid;
                int r = idx >> 2, c = idx & 3;
                cp_async16(dstb + r * ROWB + c * 16,
                           lsrc + (size_t)(lrowb + r) * HD + (kt + GSTAGES - 1) * 32 + c * 8);
            }
        }
        cp_commit();

        uint32_t stg = sb + (kt % GSTAGES) * STAGE_B;
        uint32_t aBaseH = stg + 0 * TILE_B;
        uint32_t aBaseL = stg + 1 * TILE_B;
        uint32_t bBaseH = stg + 2 * TILE_B;
        uint32_t bBaseL = stg + 3 * TILE_B;

#pragma unroll
        for (int ks = 0; ks < 2; ks++) {
            uint32_t ah[4][4], al[4][4], bh[4][2], bl[4][2];
            int arow = (lane & 15);
            int acol = (lane >> 4) * 16 + ks * 32;
#pragma unroll
            for (int mt = 0; mt < 4; mt++) {
                ldsm_x4(ah[mt], aBaseH + (wm + mt * 16 + arow) * ROWB + acol);
                ldsm_x4(al[mt], aBaseL + (wm + mt * 16 + arow) * ROWB + acol);
            }
            int brow = ((lane >> 4) << 3) + (lane & 7);
            int bcol = ((lane >> 3) & 1) * 16 + ks * 32;
#pragma unroll
            for (int p = 0; p < 2; p++) {
                uint32_t t[4];
                ldsm_x4(t, bBaseH + (wn + p * 16 + brow) * ROWB + bcol);
                bh[2 * p][0] = t[0]; bh[2 * p][1] = t[1];
                bh[2 * p + 1][0] = t[2]; bh[2 * p + 1][1] = t[3];
                ldsm_x4(t, bBaseL + (wn + p * 16 + brow) * ROWB + bcol);
                bl[2 * p][0] = t[0]; bl[2 * p][1] = t[1];
                bl[2 * p + 1][0] = t[2]; bl[2 * p + 1][1] = t[3];
            }
#pragma unroll
            for (int mt = 0; mt < 4; mt++)
#pragma unroll
                for (int nt = 0; nt < 4; nt++) {
                    mma_bf16(acc[mt][nt], ah[mt], bh[nt]);
                    mma_bf16(acc[mt][nt], ah[mt], bl[nt]);
                    mma_bf16(acc[mt][nt], al[mt], bh[nt]);
                }
        }
    }

#pragma unroll
    for (int mt = 0; mt < 4; mt++) {
#pragma unroll
        for (int nt = 0; nt < 4; nt++) {
            int m0 = bm + wm + mt * 16 + (lane >> 2);
            int n0 = bn + wn + nt * 8 + (lane & 3) * 2;
            float b0 = bias[n0], b1 = bias[n0 + 1];
            float2 v0 = make_float2(acc[mt][nt][0] + b0, acc[mt][nt][1] + b1);
            float2 v1 = make_float2(acc[mt][nt][2] + b0, acc[mt][nt][3] + b1);
            *(float2*)&C[(size_t)m0 * HD + n0] = v0;
            *(float2*)&C[(size_t)(m0 + 8) * HD + n0] = v1;
        }
    }
}

// =================================================================
// Persistent recurrent scan v10 (R15 + dual Wh acc chains + no syncD):
//  phase1: Wh MMA (2 chains) -> reduce1 -> gelu -> publish -> release
//  phase2: Wo MMA + spill2(plane2) -> poll -> frag prefetch ->
//          reduce2 + outproj store.  Planes double-buffered: syncD removed.
// =================================================================
__device__ __forceinline__ float gelu_exact(float x) {
    return 0.5f * x * (1.0f + erff(x * 0.70710678118654752f));
}

#define SROW       2064      // padded weight smem row (1032 bf16)
#define OFF_WHI    0
#define OFF_WLO    66048     // 32*2064
#define OFF_PART   132096
#define SPW        264       // floats per warp partial row
#define SCAN_SMEM  (OFF_PART + 32 * SPW * 4)   // 165888 B (2 planes)

__global__ __launch_bounds__(512)
void scan_kernel(const float* __restrict__ xproj,
                 const float* __restrict__ Wh,
                 const float* __restrict__ Wo,
                 const float* __restrict__ bo,
                 float* __restrict__ hidden,
                 float* __restrict__ outproj) {
    extern __shared__ char smem[];
    const uint32_t sb = smem_u32(smem);
    float* sPart1 = (float*)(smem + OFF_PART);
    float* sPart2 = sPart1 + 16 * SPW;

    const int tid  = threadIdx.x;
    const int w    = tid >> 5;          // warp 0..15: k slice [64w, 64w+64)
    const int lane = tid & 31;
    const int grp  = blockIdx.x >> 5;   // 0..3
    const int rank = blockIdx.x & 31;   // 0..31
    const int o0   = rank * 32;
    const int b0   = grp * 8;

    // ---- fill weight planes with Wh (hi/lo split) ----
    const float4* Wh4 = (const float4*)Wh;
    for (int i = tid; i < 8192; i += 512) {
        int r = i >> 8, c4 = i & 255;
        float4 v = Wh4[(o0 + r) * 256 + c4];
        __nv_bfloat16 h0 = __float2bfloat16(v.x);
        __nv_bfloat16 h1 = __float2bfloat16(v.y);
        __nv_bfloat16 h2 = __float2bfloat16(v.z);
        __nv_bfloat16 h3 = __float2bfloat16(v.w);
        char* dh = smem + OFF_WHI + r * SROW + c4 * 8;
        char* dl = smem + OFF_WLO + r * SROW + c4 * 8;
        *(__nv_bfloat162*)(dh)     = __halves2bfloat162(h0, h1);
        *(__nv_bfloat162*)(dh + 4) = __halves2bfloat162(h2, h3);
        *(__nv_bfloat162*)(dl)     = __halves2bfloat162(
            __float2bfloat16(v.x - __bfloat162float(h0)),
            __float2bfloat16(v.y - __bfloat162float(h1)));
        *(__nv_bfloat162*)(dl + 4) = __halves2bfloat162(
            __float2bfloat16(v.z - __bfloat162float(h2)),
            __float2bfloat16(v.w - __bfloat162float(h3)));
    }
    __syncthreads();

    // ---- Wh frags -> registers (resident) ----
    const uint32_t aBase = sb + (lane & 15) * SROW + (lane >> 4) * 16 + w * 128;
    uint32_t aHi[2][4][4], aLo[2][4][4];
#pragma unroll
    for (int mt = 0; mt < 2; mt++)
#pragma unroll
        for (int ks = 0; ks < 4; ks++) {
            ldsm_x4(aHi[mt][ks], aBase + OFF_WHI + mt * 16 * SROW + ks * 32);
            ldsm_x4(aLo[mt][ks], aBase + OFF_WLO + mt * 16 * SROW + ks * 32);
        }
    __syncthreads();

    // ---- overwrite planes with Wo (same layout), ldsm'd per step ----
    const float4* Wo4 = (const float4*)Wo;
    for (int i = tid; i < 8192; i += 512) {
        int r = i >> 8, c4 = i & 255;
        float4 v = Wo4[(o0 + r) * 256 + c4];
        __nv_bfloat16 h0 = __float2bfloat16(v.x);
        __nv_bfloat16 h1 = __float2bfloat16(v.y);
        __nv_bfloat16 h2 = __float2bfloat16(v.z);
        __nv_bfloat16 h3 = __float2bfloat16(v.w);
        char* dh = smem + OFF_WHI + r * SROW + c4 * 8;
        char* dl = smem + OFF_WLO + r * SROW + c4 * 8;
        *(__nv_bfloat162*)(dh)     = __halves2bfloat162(h0, h1);
        *(__nv_bfloat162*)(dh + 4) = __halves2bfloat162(h2, h3);
        *(__nv_bfloat162*)(dl)     = __halves2bfloat162(
            __float2bfloat16(v.x - __bfloat162float(h0)),
            __float2bfloat16(v.y - __bfloat162float(h1)));
        *(__nv_bfloat162*)(dl + 4) = __halves2bfloat162(
            __float2bfloat16(v.z - __bfloat162float(h2)),
            __float2bfloat16(v.w - __bfloat162float(h3)));
    }
    __syncthreads();

    // reduce mapping: out = o_local*8 + b_local, 2 threads per output
    const int out   = tid >> 1;          // 0..255
    const int halfq = tid & 1;
    const int ol    = out >> 3;          // 0..31
    const int bl    = out & 7;           // 0..7
    const size_t hrow = (size_t)(b0 + bl) * STEPS;

    float xv  = (halfq == 0) ? xproj[(hrow + 0) * HD + o0 + ol] : 0.f;
    float bov = (halfq == 0) ? bo[o0 + ol] : 0.f;

    // producer exchange addresses (parity 0/1), fragment-order layout
    uint8_t *pex0 = 0, *pex1 = 0;
    {
        int kg = o0 + ol;
        int g  = kg >> 4;
        int j  = (kg & 15) >> 1;
        int p  = 2 * (j & 3) + (j >> 2);
        int off = g * 512 + bl * 64 + p * 8;
        pex0 = g_ex[0][grp] + off;
        pex1 = g_ex[1][grp] + off;
    }
    const int coff = (4 * w) * 512 + (lane >> 2) * 64 + (lane & 3) * 16;

    uint4 vf0, vf1, vf2, vf3;    // h frags of step s-1 (persistent)

    for (int s = 0; s <= STEPS; s++) {
        float hval = 0.f;
        float xnext = 0.f;

        // ================= phase1: Wh path (critical) =================
        if (s < STEPS) {
            float accA[2][4], accB[2][4];
#pragma unroll
            for (int mt = 0; mt < 2; mt++)
#pragma unroll
                for (int e = 0; e < 4; e++) { accA[mt][e] = 0.f; accB[mt][e] = 0.f; }

            if (s > 0) {
                // two independent 6-MMA chains per mt (halves dep latency)
#pragma unroll
                for (int mt = 0; mt < 2; mt++) {
                    mma_bf16_2(accA[mt], aHi[mt][0], vf0.x, vf0.z);
                    mma_bf16_2(accB[mt], aHi[mt][2], vf2.x, vf2.z);
                    mma_bf16_2(accA[mt], aHi[mt][0], vf0.y, vf0.w);
                    mma_bf16_2(accB[mt], aHi[mt][2], vf2.y, vf2.w);
                    mma_bf16_2(accA[mt], aLo[mt][0], vf0.x, vf0.z);
                    mma_bf16_2(accB[mt], aLo[mt][2], vf2.x, vf2.z);
                    mma_bf16_2(accA[mt], aHi[mt][1], vf1.x, vf1.z);
                    mma_bf16_2(accB[mt], aHi[mt][3], vf3.x, vf3.z);
                    mma_bf16_2(accA[mt], aHi[mt][1], vf1.y, vf1.w);
                    mma_bf16_2(accB[mt], aHi[mt][3], vf3.y, vf3.w);
                    mma_bf16_2(accA[mt], aLo[mt][1], vf1.x, vf1.z);
                    mma_bf16_2(accB[mt], aLo[mt][3], vf3.x, vf3.z);
                }
            }
            {
                float* pw = sPart1 + w * SPW;
#pragma unroll
                for (int mt = 0; mt < 2; mt++)
#pragma unroll
                    for (int e = 0; e < 4; e++) {
                        int o = mt * 16 + (lane >> 2) + ((e >> 1) << 3);
                        int b = (lane & 3) * 2 + (e & 1);
                        pw[o * 8 + b] = accA[mt][e] + accB[mt][e];
                    }
            }
            __syncthreads();                           // sync A

            float v = 0.f;
#pragma unroll
            for (int q = 0; q < 8; q++)
                v += sPart1[(halfq * 8 + q) * SPW + out];
            v += __shfl_xor_sync(0xFFFFFFFFu, v, 1);

            uint32_t bhu = 0, bbu = 0;
            if (halfq == 0) {
                v += xv;
                hval = gelu_exact(v);
                __nv_bfloat16 bh = __float2bfloat16(hval);
                __nv_bfloat16 bb = __float2bfloat16(hval - __bfloat162float(bh));
                bhu = *(unsigned short*)&bh;
                bbu = *(unsigned short*)&bb;
            }
            uint32_t obh = __shfl_xor_sync(0xFFFFFFFFu, bhu, 16);
            uint32_t obb = __shfl_xor_sync(0xFFFFFFFFu, bbu, 16);
            if (halfq == 0 && (tid & 16) == 0) {
                unsigned long long val =
                    (unsigned long long)(bhu | (obh << 16)) |
                    ((unsigned long long)(bbu | (obb << 16)) << 32);
                *(unsigned long long*)((s & 1) ? pex1 : pex0) = val;
            }
            __syncthreads();                           // sync B (publish visible)

            if (tid == 0)
                asm volatile("red.release.gpu.global.add.u32 [%0], %1;"
                             :: "l"(&g_bar2[grp][s]), "r"(1u) : "memory");
            if (halfq == 0) {
                hidden[(hrow + s) * HD + o0 + ol] = hval;
                if (s + 1 < STEPS)
                    xnext = xproj[(hrow + s + 1) * HD + o0 + ol];
            }
        }

        // ========== phase2: Wo MMA + spill2 (barrier shadow) ==========
        if (s > 0) {
            float acc2[2][4];
#pragma unroll
            for (int mt = 0; mt < 2; mt++)
#pragma unroll
                for (int e = 0; e < 4; e++) acc2[mt][e] = 0.f;
#pragma unroll
            for (int mt = 0; mt < 2; mt++) {
#pragma unroll
                for (int ks = 0; ks < 4; ks++) {
                    uint32_t oh[4], olo[4];
                    ldsm_x4(oh,  aBase + OFF_WHI + mt * 16 * SROW + ks * 32);
                    ldsm_x4(olo, aBase + OFF_WLO + mt * 16 * SROW + ks * 32);
                    uint4 vv = (ks == 0) ? vf0 : (ks == 1) ? vf1 : (ks == 2) ? vf2 : vf3;
                    mma_bf16_2(acc2[mt], oh,  vv.x, vv.z);
                    mma_bf16_2(acc2[mt], oh,  vv.y, vv.w);
                    mma_bf16_2(acc2[mt], olo, vv.x, vv.z);
                }
            }
            {
                float* pw = sPart2 + w * SPW;
#pragma unroll
                for (int mt = 0; mt < 2; mt++)
#pragma unroll
                    for (int e = 0; e < 4; e++) {
                        int o = mt * 16 + (lane >> 2) + ((e >> 1) << 3);
                        int b = (lane & 3) * 2 + (e & 1);
                        pw[o * 8 + b] = acc2[mt][e];
                    }
            }
        }

        // ========== poll (overlaps other warps' spill2 drain) ==========
        if (s < STEPS && tid == 0) {
            unsigned int cnt;
            do {
                asm volatile("ld.acquire.gpu.global.u32 %0, [%1];"
                             : "=r"(cnt) : "l"(&g_bar2[grp][s]) : "memory");
            } while (cnt < GRP_CTAS);
        }
        __syncthreads();                               // sync C (h_s + spill2 ready)

        // ---- prefetch h_s frags immediately; work below hides latency ----
        if (s < STEPS) {
            const uint8_t* exr = g_ex[s & 1][grp] + coff;
            vf0 = __ldcg((const uint4*)(exr + 0 * 512));
            vf1 = __ldcg((const uint4*)(exr + 1 * 512));
            vf2 = __ldcg((const uint4*)(exr + 2 * 512));
            vf3 = __ldcg((const uint4*)(exr + 3 * 512));
            xv = xnext;
        }

        // ---- reduce plane2 -> outproj row s-1 (under frag LDG shadow) ----
        if (s > 0) {
            float v2 = 0.f;
#pragma unroll
            for (int q = 0; q < 8; q++)
                v2 += sPart2[(halfq * 8 + q) * SPW + out];
            v2 += __shfl_xor_sync(0xFFFFFFFFu, v2, 1);
            if (halfq == 0)
                outproj[(hrow + s - 1) * HD + o0 + ol] = v2 + bov;
        }
        // no sync D: plane1/plane2 double-buffered; syncA/syncB of the next
        // iteration order all cross-step plane reuse.
    }
}

// =================================================================
extern "C" void kernel_launch(void* const* d_in, const int* in_sizes, int n_in,
                              void* d_out, int out_size) {
    const float* seq = (const float*)d_in[0];   // (B,T,D)
    const float* Wi  = (const float*)d_in[1];   // (H,D)
    const float* bi  = (const float*)d_in[2];   // (H,)
    const float* Wh  = (const float*)d_in[3];   // (H,H)
    const float* Wo  = (const float*)d_in[4];   // (H,H)
    const float* bo  = (const float*)d_in[5];   // (H,)

    float* out     = (float*)d_out;
    float* hidden  = out;                          // (B,T,H)
    float* outproj = out + (size_t)BT * HD;        // (B,T,H)

    void *xp_addr = 0, *bar_addr = 0, *ahi = 0, *alo = 0, *bhi = 0, *blo = 0;
    cudaGetSymbolAddress(&xp_addr, g_xproj);
    cudaGetSymbolAddress(&bar_addr, g_bar2);
    cudaGetSymbolAddress(&ahi, g_Ahi);
    cudaGetSymbolAddress(&alo, g_Alo);
    cudaGetSymbolAddress(&bhi, g_Bhi);
    cudaGetSymbolAddress(&blo, g_Blo);

    cudaMemsetAsync(bar_addr, 0, 4 * STEPS * sizeof(unsigned int));

    const int nA4 = BT * HD / 4;       // 8388608
    const int nW4 = HD * HD / 4;       // 262144
    const int gemm_smem = GSTAGES * STAGE_B;   // 122880
    cudaFuncSetAttribute(mma_gemm, cudaFuncAttributeMaxDynamicSharedMemorySize, gemm_smem);
    dim3 ggrid(HD / 128, BT / 128);    // (8, 256)

    // 1) input projection: xproj = seq @ Wi^T + bi  (split-bf16 HMMA)
    split_bf16<<<nA4 / 256, 256>>>(seq, (__nv_bfloat16*)ahi, (__nv_bfloat16*)alo, nA4);
    split_bf16<<<nW4 / 256, 256>>>(Wi, (__nv_bfloat16*)bhi, (__nv_bfloat16*)blo, nW4);
    mma_gemm<<<ggrid, 256, gemm_smem>>>((const __nv_bfloat16*)ahi, (const __nv_bfloat16*)alo,
                                        (const __nv_bfloat16*)bhi, (const __nv_bfloat16*)blo,
                                        bi, (float*)xp_addr);

    // 2) recurrent scan + fused output projection
    cudaFuncSetAttribute(scan_kernel, cudaFuncAttributeMaxDynamicSharedMemorySize, SCAN_SMEM);
    scan_kernel<<<NCTA, 512, SCAN_SMEM>>>((const float*)xp_addr, Wh, Wo, bo,
                                          hidden, outproj);
}